// round 2
// baseline (speedup 1.0000x reference)
#include <cuda_runtime.h>
#include <stdint.h>
#include <math.h>

#define HH 512
#define WW 512
#define HWV (HH*WW)
#define NB 16
#define NB0 8
#define MM 2048
#define SCAP 32768

// ---------------- device scratch (static; no runtime allocation) ----------------
__device__ float g_G[25];           // normalized gaussian taps (S=25)
__device__ float g_WC[51];          // coverage taps (CS=51, unnormalized)
__device__ float g_kp[NB*HWV];      // softmax probabilities kp_p
__device__ float g_t1[NB*HWV];      // conv temp
__device__ float g_v[NB*HWV];       // v = log(s+1e-8); later reused as rowmax
__device__ float g_sd[NB*HWV];      // blurred has_depth
__device__ float g_sm2[NB*HWV];     // coverage-reweighted scoremap
__device__ float g_match[NB];
__device__ float g_sparse[NB];
__device__ int   g_svcnt[NB];
__device__ float g_svval[NB*SCAP];
__device__ int   g_svidx[NB*SCAP];
__device__ int   g_kidx[NB*MM];

// ---------------- block reduction helpers ----------------
__device__ __forceinline__ float blkMax(float v, float* red) {
  int t = threadIdx.x;
  red[t] = v; __syncthreads();
  for (int s = blockDim.x >> 1; s > 0; s >>= 1) {
    if (t < s) red[t] = fmaxf(red[t], red[t + s]);
    __syncthreads();
  }
  float r = red[0]; __syncthreads();
  return r;
}
__device__ __forceinline__ float blkSum(float v, float* red) {
  int t = threadIdx.x;
  red[t] = v; __syncthreads();
  for (int s = blockDim.x >> 1; s > 0; s >>= 1) {
    if (t < s) red[t] += red[t + s];
    __syncthreads();
  }
  float r = red[0]; __syncthreads();
  return r;
}

// ---------------- init: taps + counters ----------------
__global__ void k_init() {
  if (threadIdx.x == 0) {
    float g[25]; float s = 0.f;
    for (int i = 0; i < 25; i++) {
      float x = -1.0f + (2.0f / 24.0f) * (float)i;
      g[i] = expf(-x * x / 0.5f);
      s += g[i];
    }
    for (int i = 0; i < 25; i++) g_G[i] = g[i] / s;
    for (int i = 0; i < 51; i++) {
      float x = -2.0f + (4.0f / 50.0f) * (float)i;
      g_WC[i] = expf(-x * x);
    }
  }
  if (threadIdx.x < NB) g_svcnt[threadIdx.x] = 0;
}

// ---------------- per-image softmax over HW ----------------
__global__ __launch_bounds__(1024) void k_softmax(const float* __restrict__ x) {
  __shared__ float red[1024];
  int b = blockIdx.x, t = threadIdx.x;
  const float* in = x + (size_t)b * HWV;
  float* out = g_kp + (size_t)b * HWV;
  float mv = -INFINITY;
  for (int i = t; i < HWV; i += 1024) mv = fmaxf(mv, in[i]);
  mv = blkMax(mv, red);
  float z = 0.f;
  for (int i = t; i < HWV; i += 1024) { float e = expf(in[i] - mv); out[i] = e; z += e; }
  z = blkSum(z, red);
  float inv = 1.0f / z;
  for (int i = t; i < HWV; i += 1024) out[i] *= inv;
}

// ---------------- horizontal conv (zero padding along W) ----------------
// MODE_IN: 0 plain, 1: x -> (x+1e-6)*1e4 before conv
// ZB: 1 -> zero outputs at w<R or w>=W-R (the reference's asymmetric-padding bug)
template<int R, int MODE_IN, int ZB>
__global__ void k_hconv(const float* __restrict__ in, float* __restrict__ out,
                        const float* __restrict__ taps) {
  __shared__ float sh[256 + 2 * R];
  __shared__ float st[2 * R + 1];
  int b = blockIdx.z, h = blockIdx.y, w0 = blockIdx.x * 256;
  int t = threadIdx.x;
  const float* row = in + (size_t)b * HWV + (size_t)h * WW;
  for (int i = t; i < 2 * R + 1; i += 256) st[i] = taps[i];
  for (int i = t; i < 256 + 2 * R; i += 256) {
    int p = w0 - R + i;
    float x = 0.f;
    if (p >= 0 && p < WW) {
      x = row[p];
      if (MODE_IN == 1) x = (x + 1e-6f) * 1e4f;
    }
    sh[i] = x;
  }
  __syncthreads();
  int w = w0 + t;
  float acc = 0.f;
#pragma unroll
  for (int j = 0; j <= 2 * R; j++) acc += st[j] * sh[t + j];
  if (ZB && (w < R || w >= WW - R)) acc = 0.f;
  out[(size_t)b * HWV + (size_t)h * WW + w] = acc;
}

// ---------------- vertical conv (zero padding along H), shared-tiled ----------------
// MODE: 0 plain; 1: out=log(acc+1e-8); 2: out = aux * (acc+1e-8)^(-1/2)
template<int R, int MODE>
__global__ void k_vconv(const float* __restrict__ in, float* __restrict__ out,
                        const float* __restrict__ taps, const float* __restrict__ aux) {
  const int TH = 64;
  __shared__ float sh[(TH + 2 * R) * 32];
  __shared__ float st[2 * R + 1];
  int b = blockIdx.z, h0 = blockIdx.y * TH, w0 = blockIdx.x * 32;
  int tx = threadIdx.x, ty = threadIdx.y;
  int t = ty * 32 + tx;
  for (int i = t; i < 2 * R + 1; i += 256) st[i] = taps[i];
  const float* img = in + (size_t)b * HWV;
  for (int i = t; i < (TH + 2 * R) * 32; i += 256) {
    int r = i >> 5, c = i & 31;
    int hh = h0 - R + r;
    sh[i] = (hh >= 0 && hh < HH) ? img[(size_t)hh * WW + w0 + c] : 0.f;
  }
  __syncthreads();
  for (int s = 0; s < TH / 8; s++) {
    int hr = ty + s * 8;
    float acc = 0.f;
#pragma unroll
    for (int j = 0; j <= 2 * R; j++) acc += st[j] * sh[(hr + j) * 32 + tx];
    size_t oi = (size_t)b * HWV + (size_t)(h0 + hr) * WW + w0 + tx;
    if (MODE == 0) out[oi] = acc;
    else if (MODE == 1) out[oi] = logf(acc + 1e-8f);
    else out[oi] = aux[oi] / sqrtf(acc + 1e-8f);
  }
}

// ---------------- matchability reduction per image ----------------
__global__ __launch_bounds__(1024) void k_match() {
  __shared__ float red[1024];
  int b = blockIdx.x, t = threadIdx.x;
  const float* v = g_v + (size_t)b * HWV;
  const float* sd = g_sd + (size_t)b * HWV;
  float mv = -INFINITY, ssd = 0.f;
  for (int i = t; i < HWV; i += 1024) { mv = fmaxf(mv, v[i]); ssd += sd[i]; }
  mv = blkMax(mv, red);
  ssd = blkSum(ssd, red);
  float inv = 1.0f / ssd;
  float z = 0.f, pv = 0.f, plp = 0.f;
  for (int i = t; i < HWV; i += 1024) {
    float vi = v[i];
    z += expf(vi - mv);
    float p = sd[i] * inv;
    if (p > 0.f) { pv += p * vi; plp += p * logf(fmaxf(p, 1e-30f)); }
  }
  z = blkSum(z, red);
  pv = blkSum(pv, red);
  plp = blkSum(plp, red);
  // sum p*(log p - log_p_hat) = sum p log p - sum p v + LSE(v)   (since sum p = 1)
  if (t == 0) g_match[b] = plp - pv + (mv + logf(z));
}

// ---------------- separable 5x5 NMS ----------------
__global__ void k_rowmax(const float* __restrict__ in, float* __restrict__ out) {
  int b = blockIdx.z, h = blockIdx.y;
  int w = blockIdx.x * 256 + threadIdx.x;
  const float* row = in + (size_t)b * HWV + (size_t)h * WW;
  float m = -INFINITY;
#pragma unroll
  for (int d = -2; d <= 2; d++) {
    int p = w + d;
    if (p >= 0 && p < WW) m = fmaxf(m, row[p]);
  }
  out[(size_t)b * HWV + (size_t)h * WW + w] = m;
}

__global__ void k_nms(const float* __restrict__ sm2, const float* __restrict__ rm) {
  int b = blockIdx.z, h = blockIdx.y;
  int w = blockIdx.x * 256 + threadIdx.x;
  size_t base = (size_t)b * HWV;
  float m = -INFINITY;
#pragma unroll
  for (int d = -2; d <= 2; d++) {
    int p = h + d;
    if (p >= 0 && p < HH) m = fmaxf(m, rm[base + (size_t)p * WW + w]);
  }
  float val = sm2[base + (size_t)h * WW + w];
  if (val == m) {  // survivor (all values > 0, suppressed would be excluded)
    int p = atomicAdd(&g_svcnt[b], 1);
    if (p < SCAP) {
      g_svval[(size_t)b * SCAP + p] = val;
      g_svidx[(size_t)b * SCAP + p] = h * WW + w;
    }
  }
}

// ---------------- exact top-2048 per image via 4x8-bit radix select ----------------
__global__ __launch_bounds__(1024) void k_topk() {
  int b = blockIdx.x;
  int n = g_svcnt[b]; if (n > SCAP) n = SCAP;
  const float* vals = g_svval + (size_t)b * SCAP;
  const int* idxs = g_svidx + (size_t)b * SCAP;
  int* out = g_kidx + (size_t)b * MM;
  __shared__ int hist[256];
  __shared__ int sh_k, sh_dig, sh_ngt, sh_neq;
  int t = threadIdx.x;
  unsigned int prefix = 0;
  int k = MM;
  for (int lvl = 0; lvl < 4; lvl++) {
    int shift = 24 - 8 * lvl;
    for (int i = t; i < 256; i += 1024) hist[i] = 0;
    __syncthreads();
    for (int i = t; i < n; i += 1024) {
      unsigned int u = __float_as_uint(vals[i]);   // all vals >= 0 -> order-preserving
      bool ok = (lvl == 0) || ((u >> (shift + 8)) == (prefix >> (shift + 8)));
      if (ok) atomicAdd(&hist[(u >> shift) & 255], 1);
    }
    __syncthreads();
    if (t == 0) {
      int acc = 0, d;
      for (d = 255; d >= 0; d--) {
        if (acc + hist[d] >= k) break;
        acc += hist[d];
      }
      if (d < 0) d = 0;
      sh_k = k - acc; sh_dig = d;
    }
    __syncthreads();
    k = sh_k;
    prefix |= ((unsigned int)sh_dig) << shift;
    __syncthreads();
  }
  unsigned int T = prefix;
  if (t == 0) { sh_ngt = 0; sh_neq = 0; }
  __syncthreads();
  for (int i = t; i < n; i += 1024) {
    unsigned int u = __float_as_uint(vals[i]);
    if (u > T) { int p = atomicAdd(&sh_ngt, 1); if (p < MM) out[p] = idxs[i]; }
  }
  __syncthreads();
  int base = sh_ngt;
  for (int i = t; i < n; i += 1024) {
    unsigned int u = __float_as_uint(vals[i]);
    if (u == T) { int p = atomicAdd(&sh_neq, 1); if (base + p < MM) out[base + p] = idxs[i]; }
  }
}

// ---------------- sparse RL loss per (batch, direction) ----------------
__global__ __launch_bounds__(1024) void k_sparse(const float* __restrict__ scoremap,
                                                 const float* __restrict__ wA,
                                                 const float* __restrict__ wB,
                                                 const float* __restrict__ vA,
                                                 const float* __restrict__ vB) {
  __shared__ float sx[MM], sy[MM], ssl[MM], sr[MM];
  __shared__ unsigned char slg[MM];
  __shared__ float red[1024];
  int x = blockIdx.x;
  int dir = (x >= NB0) ? 1 : 0;  // 0: A->B, 1: B->A
  int b = dir ? x - NB0 : x;
  const int* own = g_kidx + (size_t)(dir ? (NB0 + b) : b) * MM;
  const int* opp = g_kidx + (size_t)(dir ? b : (NB0 + b)) * MM;
  const float* warp = (dir ? wB : wA) + (size_t)b * HWV * 4;
  const float* valid = (dir ? vB : vA) + (size_t)b * HWV;
  const float* logit = scoremap + (size_t)(dir ? (NB0 + b) : b) * HWV;
  int t = threadIdx.x;
  // opposite keypoints' normalized coords (keypoints sit exactly on pixel centers)
  for (int i = t; i < MM; i += 1024) {
    int id = opp[i]; int hh = id >> 9, ww = id & 511;
    sx[i] = ((float)ww + 0.5f) * (2.0f / (float)WW) - 1.0f;
    sy[i] = ((float)hh + 0.5f) * (2.0f / (float)HH) - 1.0f;
  }
  __syncthreads();
  for (int i = t; i < MM; i += 1024) {
    int id = own[i]; int hh = id >> 9, ww = id & 511;
    const float* wp = warp + (size_t)(hh * WW + ww) * 4;
    float txc = wp[2], tyc = wp[3];
    float dmin = 3.4e38f;
    for (int j = 0; j < MM; j++) {
      float dx = txc - sx[j], dy = tyc - sy[j];
      dmin = fminf(dmin, dx * dx + dy * dy);
    }
    sr[i] = expf(-100.0f * sqrtf(dmin + 1e-12f));
    slg[i] = (valid[hh * WW + ww] > 0.f) ? 1 : 0;
    ssl[i] = logit[hh * WW + ww];
  }
  __syncthreads();
  float mv = -INFINITY;
  for (int i = t; i < MM; i += 1024) { float ml = slg[i] ? ssl[i] : -1e9f; mv = fmaxf(mv, ml); }
  mv = blkMax(mv, red);
  float z = 0.f;
  for (int i = t; i < MM; i += 1024) { float ml = slg[i] ? ssl[i] : -1e9f; z += expf(ml - mv); }
  z = blkSum(z, red);
  float lse = mv + logf(z);
  float acc = 0.f;
  for (int i = t; i < MM; i += 1024) if (slg[i]) acc += sr[i] * (ssl[i] - lse);
  acc = blkSum(acc, red);
  if (t == 0) g_sparse[x] = -acc;
}

// ---------------- final combine ----------------
__global__ void k_final(float* out) {
  if (threadIdx.x == 0 && blockIdx.x == 0) {
    float s = 0.f; for (int i = 0; i < NB; i++) s += g_sparse[i];
    float m = 0.f; for (int i = 0; i < NB; i++) m += g_match[i];
    out[0] = s + m * (1.0f / 16.0f);
  }
}

// ---------------- host launcher ----------------
extern "C" void kernel_launch(void* const* d_in, const int* in_sizes, int n_in,
                              void* d_out, int out_size) {
  (void)in_sizes; (void)n_in; (void)out_size;
  const float* scoremap = (const float*)d_in[0];
  const float* wA = (const float*)d_in[1];
  const float* wB = (const float*)d_in[2];
  const float* vA = (const float*)d_in[3];
  const float* vB = (const float*)d_in[4];
  const float* hd = (const float*)d_in[5];
  float* out = (float*)d_out;

  void *p_kp = 0, *p_t1 = 0, *p_v = 0, *p_sd = 0, *p_sm2 = 0, *p_G = 0, *p_WC = 0;
  cudaGetSymbolAddress(&p_kp, g_kp);
  cudaGetSymbolAddress(&p_t1, g_t1);
  cudaGetSymbolAddress(&p_v, g_v);
  cudaGetSymbolAddress(&p_sd, g_sd);
  cudaGetSymbolAddress(&p_sm2, g_sm2);
  cudaGetSymbolAddress(&p_G, g_G);
  cudaGetSymbolAddress(&p_WC, g_WC);

  dim3 hg(WW / 256, HH, NB);
  dim3 vg(WW / 32, HH / 64, NB);
  dim3 vb(32, 8);

  k_init<<<1, 32>>>();
  k_softmax<<<NB, 1024>>>(scoremap);
  // matchability: s with asymmetric-padding bug (zeroed W borders), then v = log(s+1e-8)
  k_hconv<12, 0, 1><<<hg, 256>>>((const float*)p_kp, (float*)p_t1, (const float*)p_G);
  k_vconv<12, 1><<<vg, vb>>>((const float*)p_t1, (float*)p_v, (const float*)p_G, nullptr);
  // sd: proper same-padding separable blur of has_depth
  k_hconv<12, 0, 0><<<hg, 256>>>(hd, (float*)p_t1, (const float*)p_G);
  k_vconv<12, 0><<<vg, vb>>>((const float*)p_t1, (float*)p_sd, (const float*)p_G, nullptr);
  k_match<<<NB, 1024>>>();
  // keypoints: coverage conv (input transform), reweight, NMS, top-k
  k_hconv<25, 1, 0><<<hg, 256>>>((const float*)p_kp, (float*)p_t1, (const float*)p_WC);
  k_vconv<25, 2><<<vg, vb>>>((const float*)p_t1, (float*)p_sm2, (const float*)p_WC,
                             (const float*)p_kp);
  k_rowmax<<<hg, 256>>>((const float*)p_sm2, (float*)p_v);
  k_nms<<<hg, 256>>>((const float*)p_sm2, (const float*)p_v);
  k_topk<<<NB, 1024>>>();
  k_sparse<<<NB, 1024>>>(scoremap, wA, wB, vA, vB);
  k_final<<<1, 1>>>(out);
}

// round 3
// speedup vs baseline: 1.4050x; 1.4050x over previous
#include <cuda_runtime.h>
#include <stdint.h>
#include <math.h>

#define HH 512
#define WW 512
#define HWV (HH*WW)
#define NB 16
#define NB0 8
#define MM 2048
#define SCAP 32768
#define NC 32            // reduction chunks per image
#define CHUNK (HWV/NC)   // 8192

// ---------------- device scratch ----------------
__device__ float g_G[25];
__device__ float g_WC[51];
__device__ float g_kp[NB*HWV];      // UNNORMALIZED exp(x - max)
__device__ float g_t1[NB*HWV];
__device__ float g_v[NB*HWV];       // v = log(s+1e-8); reused for sm2 staging? no, sm2 separate
__device__ float g_sd[NB*HWV];
__device__ float g_sm2[NB*HWV];
__device__ float g_invz[NB];
__device__ float g_pm[NB*NC];       // softmax partial max
__device__ float g_ps[NB*NC];       // softmax partial sums
__device__ float g_mp[NB*NC];       // match partial max(v)
__device__ float g_sdp[NB*NC];      // match partial sum(sd)
__device__ float g_pz[NB*NC];       // match partial z
__device__ float g_ppv[NB*NC];      // match partial p*v
__device__ float g_pplp[NB*NC];     // match partial p*log p
__device__ float g_mvv[NB];         // match global max(v)
__device__ int   g_svcnt[NB];
__device__ float g_svval[NB*SCAP];
__device__ int   g_svidx[NB*SCAP];
__device__ int   g_kidx[NB*MM];
__device__ float g_ssl[NB*MM];
__device__ unsigned char g_slg[NB*MM];
__device__ float g_lse[NB];
__device__ float g_spart[NB*8];

// ---------------- block reduction helpers (blockDim.x threads) ----------------
__device__ __forceinline__ float blkMax(float v, float* red) {
  int t = threadIdx.x;
  red[t] = v; __syncthreads();
  for (int s = blockDim.x >> 1; s > 0; s >>= 1) {
    if (t < s) red[t] = fmaxf(red[t], red[t + s]);
    __syncthreads();
  }
  float r = red[0]; __syncthreads();
  return r;
}
__device__ __forceinline__ float blkSum(float v, float* red) {
  int t = threadIdx.x;
  red[t] = v; __syncthreads();
  for (int s = blockDim.x >> 1; s > 0; s >>= 1) {
    if (t < s) red[t] += red[t + s];
    __syncthreads();
  }
  float r = red[0]; __syncthreads();
  return r;
}

// ---------------- init ----------------
__global__ void k_init() {
  if (threadIdx.x == 0) {
    float g[25]; float s = 0.f;
    for (int i = 0; i < 25; i++) {
      float x = -1.0f + (2.0f / 24.0f) * (float)i;
      g[i] = expf(-x * x / 0.5f);
      s += g[i];
    }
    for (int i = 0; i < 25; i++) g_G[i] = g[i] / s;
    for (int i = 0; i < 51; i++) {
      float x = -2.0f + (4.0f / 50.0f) * (float)i;
      g_WC[i] = expf(-x * x);
    }
  }
  if (threadIdx.x < NB) g_svcnt[threadIdx.x] = 0;
}

// ---------------- softmax phase 1: partial max ----------------
__global__ __launch_bounds__(256) void k_smax1(const float* __restrict__ x) {
  __shared__ float red[256];
  int b = blockIdx.x, c = blockIdx.y, t = threadIdx.x;
  const float* in = x + (size_t)b * HWV + (size_t)c * CHUNK;
  float mv = -INFINITY;
  for (int i = t; i < CHUNK; i += 256) mv = fmaxf(mv, in[i]);
  mv = blkMax(mv, red);
  if (t == 0) g_pm[b * NC + c] = mv;
}

// ---------------- softmax phase 2: exp + partial sum (unnormalized out) ----------------
__global__ __launch_bounds__(256) void k_exp(const float* __restrict__ x) {
  __shared__ float red[256];
  int b = blockIdx.x, c = blockIdx.y, t = threadIdx.x;
  float mv = -INFINITY;
  for (int i = t; i < NC; i += 256) mv = fmaxf(mv, g_pm[b * NC + i]);
  mv = blkMax(mv, red);
  const float* in = x + (size_t)b * HWV + (size_t)c * CHUNK;
  float* out = g_kp + (size_t)b * HWV + (size_t)c * CHUNK;
  float z = 0.f;
  for (int i = t; i < CHUNK; i += 256) { float e = expf(in[i] - mv); out[i] = e; z += e; }
  z = blkSum(z, red);
  if (t == 0) g_ps[b * NC + c] = z;
}

// ---------------- softmax phase 3: inv Z per image ----------------
__global__ void k_invz() {  // <<<1, NB*32>>>
  int t = threadIdx.x, b = t >> 5, lane = t & 31;
  float v = g_ps[b * NC + lane];
#pragma unroll
  for (int o = 16; o > 0; o >>= 1) v += __shfl_down_sync(0xffffffffu, v, o);
  if (lane == 0) g_invz[b] = 1.0f / v;
}

// ---------------- horizontal conv ----------------
// MODE_IN: 0 plain, 1: x*scale, 2: (x*scale+1e-6)*1e4
// ZB: zero outputs at w<R or w>=W-R (asymmetric-padding bug)
template<int R, int MODE_IN, int ZB>
__global__ __launch_bounds__(256) void k_hconv(const float* __restrict__ in, float* __restrict__ out,
                                               const float* __restrict__ taps) {
  __shared__ float sh[256 + 2 * R];
  __shared__ float st[2 * R + 1];
  int b = blockIdx.z, h = blockIdx.y, w0 = blockIdx.x * 256;
  int t = threadIdx.x;
  float scale = (MODE_IN == 0) ? 1.0f : g_invz[b];
  const float* row = in + (size_t)b * HWV + (size_t)h * WW;
  for (int i = t; i < 2 * R + 1; i += 256) st[i] = taps[i];
  for (int i = t; i < 256 + 2 * R; i += 256) {
    int p = w0 - R + i;
    float x = 0.f;
    if (p >= 0 && p < WW) {
      x = row[p];
      if (MODE_IN == 1) x *= scale;
      if (MODE_IN == 2) x = (x * scale + 1e-6f) * 1e4f;
    }
    sh[i] = x;
  }
  __syncthreads();
  int w = w0 + t;
  float a0 = 0.f, a1 = 0.f;
#pragma unroll
  for (int j = 0; j < 2 * R; j += 2) {
    a0 += st[j]     * sh[t + j];
    a1 += st[j + 1] * sh[t + j + 1];
  }
  a0 += st[2 * R] * sh[t + 2 * R];
  float acc = a0 + a1;
  if (ZB && (w < R || w >= WW - R)) acc = 0.f;
  out[(size_t)b * HWV + (size_t)h * WW + w] = acc;
}

// ---------------- vertical conv ----------------
// MODE: 0 plain; 1: log(acc+1e-8); 2: aux*invz / sqrt(acc+1e-8)
template<int R, int MODE>
__global__ __launch_bounds__(256) void k_vconv(const float* __restrict__ in, float* __restrict__ out,
                                               const float* __restrict__ taps,
                                               const float* __restrict__ aux) {
  const int TH = 64;
  __shared__ float sh[(TH + 2 * R) * 32];
  __shared__ float st[2 * R + 1];
  int b = blockIdx.z, h0 = blockIdx.y * TH, w0 = blockIdx.x * 32;
  int tx = threadIdx.x, ty = threadIdx.y;
  int t = ty * 32 + tx;
  for (int i = t; i < 2 * R + 1; i += 256) st[i] = taps[i];
  float invz = (MODE == 2) ? g_invz[b] : 1.0f;
  const float* img = in + (size_t)b * HWV;
  for (int i = t; i < (TH + 2 * R) * 32; i += 256) {
    int r = i >> 5, c = i & 31;
    int hh = h0 - R + r;
    sh[i] = (hh >= 0 && hh < HH) ? img[(size_t)hh * WW + w0 + c] : 0.f;
  }
  __syncthreads();
  for (int s = 0; s < TH / 8; s++) {
    int hr = ty + s * 8;
    float a0 = 0.f, a1 = 0.f;
#pragma unroll
    for (int j = 0; j < 2 * R; j += 2) {
      a0 += st[j]     * sh[(hr + j) * 32 + tx];
      a1 += st[j + 1] * sh[(hr + j + 1) * 32 + tx];
    }
    a0 += st[2 * R] * sh[(hr + 2 * R) * 32 + tx];
    float acc = a0 + a1;
    size_t oi = (size_t)b * HWV + (size_t)(h0 + hr) * WW + w0 + tx;
    if (MODE == 0) out[oi] = acc;
    else if (MODE == 1) out[oi] = logf(acc + 1e-8f);
    else out[oi] = aux[oi] * invz / sqrtf(acc + 1e-8f);
  }
}

// ---------------- matchability phase 1: partial max(v), sum(sd) ----------------
__global__ __launch_bounds__(256) void k_match1() {
  __shared__ float red[256];
  int b = blockIdx.x, c = blockIdx.y, t = threadIdx.x;
  const float* v = g_v + (size_t)b * HWV + (size_t)c * CHUNK;
  const float* sd = g_sd + (size_t)b * HWV + (size_t)c * CHUNK;
  float mv = -INFINITY, ssd = 0.f;
  for (int i = t; i < CHUNK; i += 256) { mv = fmaxf(mv, v[i]); ssd += sd[i]; }
  mv = blkMax(mv, red);
  ssd = blkSum(ssd, red);
  if (t == 0) { g_mp[b * NC + c] = mv; g_sdp[b * NC + c] = ssd; }
}

// ---------------- matchability phase 2: partial z, p*v, p*log p ----------------
__global__ __launch_bounds__(256) void k_match2() {
  __shared__ float red[256];
  int b = blockIdx.x, c = blockIdx.y, t = threadIdx.x;
  float mv = -INFINITY, ssd = 0.f;
  for (int i = t; i < NC; i += 256) { mv = fmaxf(mv, g_mp[b * NC + i]); ssd += g_sdp[b * NC + i]; }
  mv = blkMax(mv, red);
  ssd = blkSum(ssd, red);
  float inv = 1.0f / ssd;
  const float* v = g_v + (size_t)b * HWV + (size_t)c * CHUNK;
  const float* sd = g_sd + (size_t)b * HWV + (size_t)c * CHUNK;
  float z = 0.f, pv = 0.f, plp = 0.f;
  for (int i = t; i < CHUNK; i += 256) {
    float vi = v[i];
    z += expf(vi - mv);
    float p = sd[i] * inv;
    if (p > 0.f) { pv += p * vi; plp += p * logf(fmaxf(p, 1e-30f)); }
  }
  z = blkSum(z, red);
  pv = blkSum(pv, red);
  plp = blkSum(plp, red);
  if (t == 0) {
    g_pz[b * NC + c] = z; g_ppv[b * NC + c] = pv; g_pplp[b * NC + c] = plp;
    if (c == 0) g_mvv[b] = mv;
  }
}

// ---------------- fused 5x5 NMS (tiled) + survivor compaction ----------------
__global__ __launch_bounds__(256) void k_nms5(const float* __restrict__ sm2) {
  __shared__ float sh[36 * 36];
  __shared__ float rm[36 * 32];
  int b = blockIdx.z;
  int h0 = blockIdx.y * 32, w0 = blockIdx.x * 32;
  int t = threadIdx.y * 32 + threadIdx.x;
  const float* img = sm2 + (size_t)b * HWV;
  for (int i = t; i < 36 * 36; i += 256) {
    int r = i / 36, c = i - r * 36;
    int hh = h0 - 2 + r, ww = w0 - 2 + c;
    sh[i] = (hh >= 0 && hh < HH && ww >= 0 && ww < WW) ? img[(size_t)hh * WW + ww] : -INFINITY;
  }
  __syncthreads();
  for (int i = t; i < 36 * 32; i += 256) {
    int r = i >> 5, c = i & 31;
    const float* p = sh + r * 36 + c;
    float m = fmaxf(fmaxf(fmaxf(p[0], p[1]), fmaxf(p[2], p[3])), p[4]);
    rm[r * 32 + c] = m;
  }
  __syncthreads();
#pragma unroll
  for (int s = 0; s < 4; s++) {
    int r = threadIdx.y + s * 8;
    int c = threadIdx.x;
    const float* p = rm + r * 32 + c;
    float m = fmaxf(fmaxf(fmaxf(p[0], p[32]), fmaxf(p[64], p[96])), p[128]);
    float val = sh[(r + 2) * 36 + (c + 2)];
    if (val == m) {
      int pp = atomicAdd(&g_svcnt[b], 1);
      if (pp < SCAP) {
        g_svval[(size_t)b * SCAP + pp] = val;
        g_svidx[(size_t)b * SCAP + pp] = (h0 + r) * WW + (w0 + c);
      }
    }
  }
}

// ---------------- exact top-2048 via radix select ----------------
__global__ __launch_bounds__(1024) void k_topk() {
  int b = blockIdx.x;
  int n = g_svcnt[b]; if (n > SCAP) n = SCAP;
  const float* vals = g_svval + (size_t)b * SCAP;
  const int* idxs = g_svidx + (size_t)b * SCAP;
  int* out = g_kidx + (size_t)b * MM;
  __shared__ int hist[256];
  __shared__ int sh_k, sh_dig, sh_ngt, sh_neq;
  int t = threadIdx.x;
  unsigned int prefix = 0;
  int k = MM;
  for (int lvl = 0; lvl < 4; lvl++) {
    int shift = 24 - 8 * lvl;
    for (int i = t; i < 256; i += 1024) hist[i] = 0;
    __syncthreads();
    for (int i = t; i < n; i += 1024) {
      unsigned int u = __float_as_uint(vals[i]);
      bool ok = (lvl == 0) || ((u >> (shift + 8)) == (prefix >> (shift + 8)));
      if (ok) atomicAdd(&hist[(u >> shift) & 255], 1);
    }
    __syncthreads();
    if (t == 0) {
      int acc = 0, d;
      for (d = 255; d >= 0; d--) {
        if (acc + hist[d] >= k) break;
        acc += hist[d];
      }
      if (d < 0) d = 0;
      sh_k = k - acc; sh_dig = d;
    }
    __syncthreads();
    k = sh_k;
    prefix |= ((unsigned int)sh_dig) << shift;
    __syncthreads();
  }
  unsigned int T = prefix;
  if (t == 0) { sh_ngt = 0; sh_neq = 0; }
  __syncthreads();
  for (int i = t; i < n; i += 1024) {
    unsigned int u = __float_as_uint(vals[i]);
    if (u > T) { int p = atomicAdd(&sh_ngt, 1); if (p < MM) out[p] = idxs[i]; }
  }
  __syncthreads();
  int base = sh_ngt;
  for (int i = t; i < n; i += 1024) {
    unsigned int u = __float_as_uint(vals[i]);
    if (u == T) { int p = atomicAdd(&sh_neq, 1); if (base + p < MM) out[base + p] = idxs[i]; }
  }
}

// ---------------- gather logits + validity + masked LSE per (b,dir) ----------------
__global__ __launch_bounds__(256) void k_gather(const float* __restrict__ scoremap,
                                                const float* __restrict__ vA,
                                                const float* __restrict__ vB) {
  __shared__ float red[256];
  int x = blockIdx.x;
  int dir = (x >= NB0) ? 1 : 0;
  int b = dir ? x - NB0 : x;
  const int* own = g_kidx + (size_t)x * MM;
  const float* valid = (dir ? vB : vA) + (size_t)b * HWV;
  const float* logit = scoremap + (size_t)x * HWV;
  int t = threadIdx.x;
  float mv = -INFINITY;
  for (int i = t; i < MM; i += 256) {
    int id = own[i];
    float sl = logit[id];
    unsigned char lg = (valid[id] > 0.f) ? 1 : 0;
    g_ssl[(size_t)x * MM + i] = sl;
    g_slg[(size_t)x * MM + i] = lg;
    mv = fmaxf(mv, lg ? sl : -1e9f);
  }
  mv = blkMax(mv, red);
  float z = 0.f;
  for (int i = t; i < MM; i += 256) {
    float ml = g_slg[(size_t)x * MM + i] ? g_ssl[(size_t)x * MM + i] : -1e9f;
    z += expf(ml - mv);
  }
  z = blkSum(z, red);
  if (t == 0) g_lse[x] = mv + logf(z);
}

// ---------------- distance + reward + weighted loss partials ----------------
__global__ __launch_bounds__(256) void k_dist(const float* __restrict__ wA,
                                              const float* __restrict__ wB) {
  __shared__ float2 sxy[MM];
  __shared__ float red[256];
  int x = blockIdx.x, seg = blockIdx.y;
  int dir = (x >= NB0) ? 1 : 0;
  int b = dir ? x - NB0 : x;
  int oppx = dir ? b : (NB0 + b);
  const int* opp = g_kidx + (size_t)oppx * MM;
  const int* own = g_kidx + (size_t)x * MM;
  const float4* warp = (const float4*)((dir ? wB : wA) + (size_t)b * HWV * 4);
  int t = threadIdx.x;
  for (int i = t; i < MM; i += 256) {
    int id = opp[i]; int hh = id >> 9, ww = id & 511;
    sxy[i] = make_float2(((float)ww + 0.5f) * (2.0f / (float)WW) - 1.0f,
                         ((float)hh + 0.5f) * (2.0f / (float)HH) - 1.0f);
  }
  __syncthreads();
  int i = seg * 256 + t;
  int id = own[i];
  float4 wp = warp[id];
  float txc = wp.z, tyc = wp.w;
  float d0 = 3.4e38f, d1 = 3.4e38f, d2 = 3.4e38f, d3 = 3.4e38f;
#pragma unroll 2
  for (int j = 0; j < MM; j += 4) {
    float2 p0 = sxy[j], p1 = sxy[j + 1], p2 = sxy[j + 2], p3 = sxy[j + 3];
    float dx, dy;
    dx = txc - p0.x; dy = tyc - p0.y; d0 = fminf(d0, fmaf(dx, dx, dy * dy));
    dx = txc - p1.x; dy = tyc - p1.y; d1 = fminf(d1, fmaf(dx, dx, dy * dy));
    dx = txc - p2.x; dy = tyc - p2.y; d2 = fminf(d2, fmaf(dx, dx, dy * dy));
    dx = txc - p3.x; dy = tyc - p3.y; d3 = fminf(d3, fmaf(dx, dx, dy * dy));
  }
  float dmin = fminf(fminf(d0, d1), fminf(d2, d3));
  float r = expf(-100.0f * sqrtf(dmin + 1e-12f));
  float lse = g_lse[x];
  float contrib = g_slg[(size_t)x * MM + i] ? r * (g_ssl[(size_t)x * MM + i] - lse) : 0.f;
  contrib = blkSum(contrib, red);
  if (t == 0) g_spart[x * 8 + seg] = contrib;
}

// ---------------- final combine ----------------
__global__ void k_final(float* out) {
  if (threadIdx.x == 0 && blockIdx.x == 0) {
    float sp = 0.f;
    for (int i = 0; i < NB * 8; i++) sp += g_spart[i];
    float m = 0.f;
    for (int b = 0; b < NB; b++) {
      float z = 0.f, pv = 0.f, plp = 0.f;
      for (int c = 0; c < NC; c++) {
        z += g_pz[b * NC + c]; pv += g_ppv[b * NC + c]; plp += g_pplp[b * NC + c];
      }
      m += plp - pv + (g_mvv[b] + logf(z));
    }
    out[0] = -sp + m * (1.0f / 16.0f);
  }
}

// ---------------- host launcher ----------------
extern "C" void kernel_launch(void* const* d_in, const int* in_sizes, int n_in,
                              void* d_out, int out_size) {
  (void)in_sizes; (void)n_in; (void)out_size;
  const float* scoremap = (const float*)d_in[0];
  const float* wA = (const float*)d_in[1];
  const float* wB = (const float*)d_in[2];
  const float* vA = (const float*)d_in[3];
  const float* vB = (const float*)d_in[4];
  const float* hd = (const float*)d_in[5];
  float* out = (float*)d_out;

  void *p_kp = 0, *p_t1 = 0, *p_v = 0, *p_sd = 0, *p_sm2 = 0, *p_G = 0, *p_WC = 0;
  cudaGetSymbolAddress(&p_kp, g_kp);
  cudaGetSymbolAddress(&p_t1, g_t1);
  cudaGetSymbolAddress(&p_v, g_v);
  cudaGetSymbolAddress(&p_sd, g_sd);
  cudaGetSymbolAddress(&p_sm2, g_sm2);
  cudaGetSymbolAddress(&p_G, g_G);
  cudaGetSymbolAddress(&p_WC, g_WC);

  dim3 hg(WW / 256, HH, NB);
  dim3 vg(WW / 32, HH / 64, NB);
  dim3 vb(32, 8);
  dim3 rg(NB, NC);
  dim3 ng(WW / 32, HH / 32, NB);
  dim3 nb(32, 8);
  dim3 dg(NB, 8);

  k_init<<<1, 32>>>();
  k_smax1<<<rg, 256>>>(scoremap);
  k_exp<<<rg, 256>>>(scoremap);
  k_invz<<<1, NB * 32>>>();
  // matchability: s conv (asymmetric-padding bug -> zeroed W borders), v = log
  k_hconv<12, 1, 1><<<hg, 256>>>((const float*)p_kp, (float*)p_t1, (const float*)p_G);
  k_vconv<12, 1><<<vg, vb>>>((const float*)p_t1, (float*)p_v, (const float*)p_G, nullptr);
  // sd: proper same-padding blur of has_depth
  k_hconv<12, 0, 0><<<hg, 256>>>(hd, (float*)p_t1, (const float*)p_G);
  k_vconv<12, 0><<<vg, vb>>>((const float*)p_t1, (float*)p_sd, (const float*)p_G, nullptr);
  k_match1<<<rg, 256>>>();
  k_match2<<<rg, 256>>>();
  // coverage conv + reweight
  k_hconv<25, 2, 0><<<hg, 256>>>((const float*)p_kp, (float*)p_t1, (const float*)p_WC);
  k_vconv<25, 2><<<vg, vb>>>((const float*)p_t1, (float*)p_sm2, (const float*)p_WC,
                             (const float*)p_kp);
  k_nms5<<<ng, nb>>>((const float*)p_sm2);
  k_topk<<<NB, 1024>>>();
  k_gather<<<NB, 256>>>(scoremap, vA, vB);
  k_dist<<<dg, 256>>>(wA, wB);
  k_final<<<1, 1>>>(out);
}

// round 4
// speedup vs baseline: 2.3475x; 1.6709x over previous
#include <cuda_runtime.h>
#include <stdint.h>
#include <math.h>

#define HH 512
#define WW 512
#define HWV (HH*WW)
#define NB 16
#define NB0 8
#define MM 2048
#define SCAP 32768
#define NC 32
#define CHUNK (HWV/NC)

// ---------------- device scratch ----------------
__device__ float g_G[25];
__device__ float g_WC[51];
__device__ float g_t1a[NB*HWV];
__device__ float g_t1b[NB*HWV];
__device__ float g_ps[NB*NC];
__device__ float g_invz[NB];
__device__ float g_mpart[NB*128*4];   // per-block matchability partials: z, sd, sdv, sdlsd
__device__ int   g_svcnt[NB];
__device__ float g_svval[NB*SCAP];
__device__ int   g_svidx[NB*SCAP];
__device__ int   g_kidx[NB*MM];
__device__ float g_ssl[NB*MM];
__device__ unsigned char g_slg[NB*MM];
__device__ float g_lse[NB];
__device__ float g_spart[NB*8];

// ---------------- reduction helpers ----------------
__device__ __forceinline__ float blkMax(float v, float* red) {
  int t = threadIdx.x;
  red[t] = v; __syncthreads();
  for (int s = blockDim.x >> 1; s > 0; s >>= 1) {
    if (t < s) red[t] = fmaxf(red[t], red[t + s]);
    __syncthreads();
  }
  float r = red[0]; __syncthreads();
  return r;
}
__device__ __forceinline__ float blkSum(float v, float* red) {
  int t = threadIdx.x;
  red[t] = v; __syncthreads();
  for (int s = blockDim.x >> 1; s > 0; s >>= 1) {
    if (t < s) red[t] += red[t + s];
    __syncthreads();
  }
  float r = red[0]; __syncthreads();
  return r;
}
// 256-thread version using linear tid within 2D block
__device__ __forceinline__ float blkSum256(float v, float* red, int t) {
  red[t] = v; __syncthreads();
  for (int s = 128; s > 0; s >>= 1) {
    if (t < s) red[t] += red[t + s];
    __syncthreads();
  }
  float r = red[0]; __syncthreads();
  return r;
}

// ---------------- init ----------------
__global__ void k_init() {
  if (threadIdx.x == 0) {
    float g[25]; float s = 0.f;
    for (int i = 0; i < 25; i++) {
      float x = -1.0f + (2.0f / 24.0f) * (float)i;
      g[i] = expf(-x * x / 0.5f);
      s += g[i];
    }
    for (int i = 0; i < 25; i++) g_G[i] = g[i] / s;
    for (int i = 0; i < 51; i++) {
      float x = -2.0f + (4.0f / 50.0f) * (float)i;
      g_WC[i] = expf(-x * x);
    }
  }
  if (threadIdx.x < NB) g_svcnt[threadIdx.x] = 0;
}

// ---------------- softmax denominator: partial sums of exp ----------------
__global__ __launch_bounds__(256) void k_sum(const float* __restrict__ x) {
  __shared__ float red[256];
  int b = blockIdx.x, c = blockIdx.y, t = threadIdx.x;
  const float* in = x + (size_t)b * HWV + (size_t)c * CHUNK;
  float z = 0.f;
  for (int i = t; i < CHUNK; i += 256) z += __expf(in[i]);
  z = blkSum(z, red);
  if (t == 0) g_ps[b * NC + c] = z;
}

__global__ void k_invz() {  // <<<1, 512>>>
  int t = threadIdx.x, b = t >> 5, lane = t & 31;
  float v = g_ps[b * NC + lane];
#pragma unroll
  for (int o = 16; o > 0; o >>= 1) v += __shfl_down_sync(0xffffffffu, v, o);
  if (lane == 0) g_invz[b] = 1.0f / v;
}

// ---------------- horizontal conv, 8 outputs/thread, taps in regs ----------------
// MODE: 0 plain; 1 exp(x)*invz; 2 (exp(x)*invz + 1e-6)*1e4.  ZB: zero w<R or w>=W-R.
template<int R, int MODE, int ZB>
__global__ __launch_bounds__(256) void k_hconv8(const float* __restrict__ in,
                                                float* __restrict__ out,
                                                const float* __restrict__ taps) {
  constexpr int RA = (R + 3) & ~3;
  constexpr int D = RA - R;
  constexpr int RW = 512 + 2 * RA;     // multiple of 4
  constexpr int WL = 8 + 2 * RA;       // per-thread window (multiple of 4)
  __shared__ float srow[4][RW];
  int b = blockIdx.y;
  int ty = threadIdx.y, tx = threadIdx.x;
  int h = blockIdx.x * 4 + ty;
  float scale = (MODE == 0) ? 1.0f : g_invz[b];
  const float* row = in + (size_t)b * HWV + (size_t)h * WW;
  for (int c = tx; c < RW; c += 64) {
    int w = c - RA;
    float x = 0.f;
    if (w >= 0 && w < WW) {
      x = row[w];
      if (MODE == 1) x = __expf(x) * scale;
      else if (MODE == 2) x = (__expf(x) * scale + 1e-6f) * 1e4f;
    }
    srow[ty][c] = x;
  }
  __syncthreads();
  float tp[2 * R + 1];
#pragma unroll
  for (int t = 0; t < 2 * R + 1; t++) tp[t] = taps[t];
  float acc[8];
#pragma unroll
  for (int k = 0; k < 8; k++) acc[k] = 0.f;
  const float4* w4 = (const float4*)&srow[ty][8 * tx];
#pragma unroll
  for (int g = 0; g < WL / 4; g++) {
    float4 X = w4[g];
    float xs[4] = {X.x, X.y, X.z, X.w};
#pragma unroll
    for (int c = 0; c < 4; c++) {
      int q = 4 * g + c;
#pragma unroll
      for (int k = 0; k < 8; k++) {
        int t = q - D - k;
        if (t >= 0 && t <= 2 * R) acc[k] = fmaf(tp[t], xs[c], acc[k]);
      }
    }
  }
  int wbase = 8 * tx;
  if (ZB) {
#pragma unroll
    for (int k = 0; k < 8; k++) {
      int w = wbase + k;
      if (w < R || w >= WW - R) acc[k] = 0.f;
    }
  }
  float4* orow = (float4*)(out + (size_t)b * HWV + (size_t)h * WW + wbase);
  orow[0] = make_float4(acc[0], acc[1], acc[2], acc[3]);
  orow[1] = make_float4(acc[4], acc[5], acc[6], acc[7]);
}

// ---------------- fused vertical convs (s + sd) + matchability partials ----------------
__global__ __launch_bounds__(256) void k_vmatch(const float* __restrict__ t1s,
                                                const float* __restrict__ t1sd,
                                                const float* __restrict__ taps) {
  __shared__ float red[256];
  int b = blockIdx.z;
  int w = blockIdx.x * 32 + threadIdx.x;
  int hb = blockIdx.y * 64 + threadIdx.y * 8;
  int tid = threadIdx.y * 32 + threadIdx.x;
  float tp[25];
#pragma unroll
  for (int t = 0; t < 25; t++) tp[t] = taps[t];
  const float* ps = t1s + (size_t)b * HWV;
  const float* pd = t1sd + (size_t)b * HWV;
  float as[8], ad[8];
#pragma unroll
  for (int k = 0; k < 8; k++) { as[k] = 0.f; ad[k] = 0.f; }
#pragma unroll
  for (int r = 0; r < 32; r++) {
    int hh = hb - 12 + r;
    float xs = 0.f, xd = 0.f;
    if (hh >= 0 && hh < HH) {
      size_t idx = (size_t)hh * WW + w;
      xs = ps[idx]; xd = pd[idx];
    }
#pragma unroll
    for (int k = 0; k < 8; k++) {
      int t = r - k;
      if (t >= 0 && t <= 24) {
        as[k] = fmaf(tp[t], xs, as[k]);
        ad[k] = fmaf(tp[t], xd, ad[k]);
      }
    }
  }
  float zsum = 0.f, sdsum = 0.f, sdv = 0.f, sdlsd = 0.f;
#pragma unroll
  for (int k = 0; k < 8; k++) {
    float s = as[k] + 1e-8f;
    float v = __logf(s);
    zsum += s;
    float sd = ad[k];
    sdsum += sd;
    if (sd > 0.f) {
      sdv = fmaf(sd, v, sdv);
      sdlsd = fmaf(sd, __logf(sd), sdlsd);
    }
  }
  zsum = blkSum256(zsum, red, tid);
  sdsum = blkSum256(sdsum, red, tid);
  sdv = blkSum256(sdv, red, tid);
  sdlsd = blkSum256(sdlsd, red, tid);
  if (tid == 0) {
    int bi = blockIdx.y * 16 + blockIdx.x;
    float* p = g_mpart + ((size_t)b * 128 + bi) * 4;
    p[0] = zsum; p[1] = sdsum; p[2] = sdv; p[3] = sdlsd;
  }
}

// ---------------- vertical coverage conv (R=25) + reweight output ----------------
__global__ __launch_bounds__(256) void k_vcov(const float* __restrict__ t1,
                                              float* __restrict__ out,
                                              const float* __restrict__ taps,
                                              const float* __restrict__ score) {
  int b = blockIdx.z;
  int w = blockIdx.x * 32 + threadIdx.x;
  int hb = blockIdx.y * 64 + threadIdx.y * 8;
  float tp[51];
#pragma unroll
  for (int t = 0; t < 51; t++) tp[t] = taps[t];
  const float* pin = t1 + (size_t)b * HWV;
  float acc[8];
#pragma unroll
  for (int k = 0; k < 8; k++) acc[k] = 0.f;
#pragma unroll
  for (int r = 0; r < 58; r++) {
    int hh = hb - 25 + r;
    float x = 0.f;
    if (hh >= 0 && hh < HH) x = pin[(size_t)hh * WW + w];
#pragma unroll
    for (int k = 0; k < 8; k++) {
      int t = r - k;
      if (t >= 0 && t <= 50) acc[k] = fmaf(tp[t], x, acc[k]);
    }
  }
  float invz = g_invz[b];
  const float* sc = score + (size_t)b * HWV;
  float* po = out + (size_t)b * HWV;
#pragma unroll
  for (int k = 0; k < 8; k++) {
    size_t oi = (size_t)(hb + k) * WW + w;
    po[oi] = __expf(sc[oi]) * invz * rsqrtf(acc[k] + 1e-8f);
  }
}

// ---------------- fused 5x5 NMS + survivor compaction ----------------
__global__ __launch_bounds__(256) void k_nms5(const float* __restrict__ sm2) {
  __shared__ float sh[36 * 36];
  __shared__ float rm[36 * 32];
  int b = blockIdx.z;
  int h0 = blockIdx.y * 32, w0 = blockIdx.x * 32;
  int t = threadIdx.y * 32 + threadIdx.x;
  const float* img = sm2 + (size_t)b * HWV;
  for (int i = t; i < 36 * 36; i += 256) {
    int r = i / 36, c = i - r * 36;
    int hh = h0 - 2 + r, ww = w0 - 2 + c;
    sh[i] = (hh >= 0 && hh < HH && ww >= 0 && ww < WW) ? img[(size_t)hh * WW + ww] : -INFINITY;
  }
  __syncthreads();
  for (int i = t; i < 36 * 32; i += 256) {
    int r = i >> 5, c = i & 31;
    const float* p = sh + r * 36 + c;
    rm[r * 32 + c] = fmaxf(fmaxf(fmaxf(p[0], p[1]), fmaxf(p[2], p[3])), p[4]);
  }
  __syncthreads();
#pragma unroll
  for (int s = 0; s < 4; s++) {
    int r = threadIdx.y + s * 8;
    int c = threadIdx.x;
    const float* p = rm + r * 32 + c;
    float m = fmaxf(fmaxf(fmaxf(p[0], p[32]), fmaxf(p[64], p[96])), p[128]);
    float val = sh[(r + 2) * 36 + (c + 2)];
    if (val == m) {
      int pp = atomicAdd(&g_svcnt[b], 1);
      if (pp < SCAP) {
        g_svval[(size_t)b * SCAP + pp] = val;
        g_svidx[(size_t)b * SCAP + pp] = (h0 + r) * WW + (w0 + c);
      }
    }
  }
}

// ---------------- top-2048 radix select + logit/validity gather + masked LSE ----------------
__global__ __launch_bounds__(1024) void k_topk(const float* __restrict__ scoremap,
                                               const float* __restrict__ vA,
                                               const float* __restrict__ vB) {
  int x = blockIdx.x;
  int n = g_svcnt[x]; if (n > SCAP) n = SCAP;
  const float* vals = g_svval + (size_t)x * SCAP;
  const int* idxs = g_svidx + (size_t)x * SCAP;
  int* out = g_kidx + (size_t)x * MM;
  __shared__ int hist[256];
  __shared__ float red[1024];
  __shared__ int sh_k, sh_dig, sh_ngt, sh_neq;
  int t = threadIdx.x;
  unsigned int prefix = 0;
  int k = MM;
  for (int lvl = 0; lvl < 4; lvl++) {
    int shift = 24 - 8 * lvl;
    if (t < 256) hist[t] = 0;
    __syncthreads();
    for (int i = t; i < n; i += 1024) {
      unsigned int u = __float_as_uint(vals[i]);
      bool ok = (lvl == 0) || ((u >> (shift + 8)) == (prefix >> (shift + 8)));
      if (ok) atomicAdd(&hist[(u >> shift) & 255], 1);
    }
    __syncthreads();
    if (t == 0) {
      int acc = 0, d;
      for (d = 255; d >= 0; d--) {
        if (acc + hist[d] >= k) break;
        acc += hist[d];
      }
      if (d < 0) d = 0;
      sh_k = k - acc; sh_dig = d;
    }
    __syncthreads();
    k = sh_k;
    prefix |= ((unsigned int)sh_dig) << shift;
    __syncthreads();
  }
  unsigned int T = prefix;
  if (t == 0) { sh_ngt = 0; sh_neq = 0; }
  __syncthreads();
  for (int i = t; i < n; i += 1024) {
    unsigned int u = __float_as_uint(vals[i]);
    if (u > T) { int p = atomicAdd(&sh_ngt, 1); if (p < MM) out[p] = idxs[i]; }
  }
  __syncthreads();
  int base = sh_ngt;
  for (int i = t; i < n; i += 1024) {
    unsigned int u = __float_as_uint(vals[i]);
    if (u == T) { int p = atomicAdd(&sh_neq, 1); if (base + p < MM) out[base + p] = idxs[i]; }
  }
  __syncthreads();
  // ---- gather logits + validity, masked LSE ----
  int dir = (x >= NB0) ? 1 : 0;
  int b = dir ? x - NB0 : x;
  const float* valid = (dir ? vB : vA) + (size_t)b * HWV;
  const float* logit = scoremap + (size_t)x * HWV;
  float mv = -INFINITY;
  for (int i = t; i < MM; i += 1024) {
    int id = out[i];
    float sl = logit[id];
    unsigned char lg = (valid[id] > 0.f) ? 1 : 0;
    g_ssl[(size_t)x * MM + i] = sl;
    g_slg[(size_t)x * MM + i] = lg;
    mv = fmaxf(mv, lg ? sl : -1e9f);
  }
  mv = blkMax(mv, red);
  float z = 0.f;
  for (int i = t; i < MM; i += 1024) {
    float ml = g_slg[(size_t)x * MM + i] ? g_ssl[(size_t)x * MM + i] : -1e9f;
    z += expf(ml - mv);
  }
  z = blkSum(z, red);
  if (t == 0) g_lse[x] = mv + logf(z);
}

// ---------------- distance + reward + weighted loss partials ----------------
__global__ __launch_bounds__(256) void k_dist(const float* __restrict__ wA,
                                              const float* __restrict__ wB) {
  __shared__ float2 sxy[MM];
  __shared__ float red[256];
  int x = blockIdx.x, seg = blockIdx.y;
  int dir = (x >= NB0) ? 1 : 0;
  int b = dir ? x - NB0 : x;
  int oppx = dir ? b : (NB0 + b);
  const int* opp = g_kidx + (size_t)oppx * MM;
  const int* own = g_kidx + (size_t)x * MM;
  const float4* warp = (const float4*)((dir ? wB : wA) + (size_t)b * HWV * 4);
  int t = threadIdx.x;
  for (int i = t; i < MM; i += 256) {
    int id = opp[i]; int hh = id >> 9, ww = id & 511;
    sxy[i] = make_float2(((float)ww + 0.5f) * (2.0f / (float)WW) - 1.0f,
                         ((float)hh + 0.5f) * (2.0f / (float)HH) - 1.0f);
  }
  __syncthreads();
  int i = seg * 256 + t;
  int id = own[i];
  float4 wp = warp[id];
  float txc = wp.z, tyc = wp.w;
  float d0 = 3.4e38f, d1 = 3.4e38f, d2 = 3.4e38f, d3 = 3.4e38f;
#pragma unroll 2
  for (int j = 0; j < MM; j += 4) {
    float2 p0 = sxy[j], p1 = sxy[j + 1], p2 = sxy[j + 2], p3 = sxy[j + 3];
    float dx, dy;
    dx = txc - p0.x; dy = tyc - p0.y; d0 = fminf(d0, fmaf(dx, dx, dy * dy));
    dx = txc - p1.x; dy = tyc - p1.y; d1 = fminf(d1, fmaf(dx, dx, dy * dy));
    dx = txc - p2.x; dy = tyc - p2.y; d2 = fminf(d2, fmaf(dx, dx, dy * dy));
    dx = txc - p3.x; dy = tyc - p3.y; d3 = fminf(d3, fmaf(dx, dx, dy * dy));
  }
  float dmin = fminf(fminf(d0, d1), fminf(d2, d3));
  float r = expf(-100.0f * sqrtf(dmin + 1e-12f));
  float lse = g_lse[x];
  float contrib = g_slg[(size_t)x * MM + i] ? r * (g_ssl[(size_t)x * MM + i] - lse) : 0.f;
  contrib = blkSum(contrib, red);
  if (t == 0) g_spart[x * 8 + seg] = contrib;
}

// ---------------- final combine ----------------
__global__ __launch_bounds__(256) void k_final(float* __restrict__ out) {
  __shared__ float sZ[128], sS[128], sV[128], sD[128];
  __shared__ float sm[16];
  __shared__ float ssp[128];
  int t = threadIdx.x;
  if (t < 128) {
    int img = t >> 3, seg = t & 7;
    float z = 0.f, s = 0.f, v = 0.f, d = 0.f;
    for (int j = 0; j < 16; j++) {
      const float* p = g_mpart + ((size_t)img * 128 + seg * 16 + j) * 4;
      z += p[0]; s += p[1]; v += p[2]; d += p[3];
    }
    sZ[t] = z; sS[t] = s; sV[t] = v; sD[t] = d;
    ssp[t] = g_spart[t];
  }
  __syncthreads();
  if (t < 16) {
    float z = 0.f, s = 0.f, v = 0.f, d = 0.f;
    for (int seg = 0; seg < 8; seg++) {
      z += sZ[t * 8 + seg]; s += sS[t * 8 + seg];
      v += sV[t * 8 + seg]; d += sD[t * 8 + seg];
    }
    float inv = 1.0f / s;
    sm[t] = inv * (d - v) - logf(s) + logf(z);
  }
  __syncthreads();
  if (t == 0) {
    float sp = 0.f;
    for (int i = 0; i < 128; i++) sp += ssp[i];
    float m = 0.f;
    for (int i = 0; i < 16; i++) m += sm[i];
    out[0] = -sp + m * (1.0f / 16.0f);
  }
}

// ---------------- host launcher ----------------
extern "C" void kernel_launch(void* const* d_in, const int* in_sizes, int n_in,
                              void* d_out, int out_size) {
  (void)in_sizes; (void)n_in; (void)out_size;
  const float* scoremap = (const float*)d_in[0];
  const float* wA = (const float*)d_in[1];
  const float* wB = (const float*)d_in[2];
  const float* vA = (const float*)d_in[3];
  const float* vB = (const float*)d_in[4];
  const float* hd = (const float*)d_in[5];
  float* out = (float*)d_out;

  void *p_a = 0, *p_b = 0, *p_G = 0, *p_WC = 0;
  cudaGetSymbolAddress(&p_a, g_t1a);
  cudaGetSymbolAddress(&p_b, g_t1b);
  cudaGetSymbolAddress(&p_G, g_G);
  cudaGetSymbolAddress(&p_WC, g_WC);

  dim3 sg(NB, NC);
  dim3 hg(HH / 4, NB);
  dim3 hb(64, 4);
  dim3 vg(WW / 32, HH / 64, NB);
  dim3 vb(32, 8);
  dim3 ng(WW / 32, HH / 32, NB);
  dim3 nb(32, 8);
  dim3 dg(NB, 8);

  k_init<<<1, 32>>>();
  k_sum<<<sg, 256>>>(scoremap);
  k_invz<<<1, 512>>>();
  // s-chain hconv (exp*invz input, W-border-zero bug) and sd hconv (plain)
  k_hconv8<12, 1, 1><<<hg, hb>>>(scoremap, (float*)p_a, (const float*)p_G);
  k_hconv8<12, 0, 0><<<hg, hb>>>(hd, (float*)p_b, (const float*)p_G);
  // fused: both vertical R12 convs + matchability partial sums (no image writes)
  k_vmatch<<<vg, vb>>>((const float*)p_a, (const float*)p_b, (const float*)p_G);
  // coverage chain: hconv R25 on (exp*invz + 1e-6)*1e4, vconv R25 + reweight
  k_hconv8<25, 2, 0><<<hg, hb>>>(scoremap, (float*)p_a, (const float*)p_WC);
  k_vcov<<<vg, vb>>>((const float*)p_a, (float*)p_b, (const float*)p_WC, scoremap);
  k_nms5<<<ng, nb>>>((const float*)p_b);
  k_topk<<<NB, 1024>>>(scoremap, vA, vB);
  k_dist<<<dg, 256>>>(wA, wB);
  k_final<<<1, 256>>>(out);
}